// round 6
// baseline (speedup 1.0000x reference)
#include <cuda_runtime.h>
#include <cstddef>

// B=128, D=1024. d_in[0]=mu (131072 f32), d_in[1]=Sigma (128*1024*1024 f32)
// d_out = [mu_out 131072 f32 | Sigma_out 134217728 f32]

static constexpr int B = 128;
static constexpr int D = 1024;
static constexpr int ROWS = 4;   // Sigma rows per block

// 256-bit global load/store (sm_100+: LDG.E.256 / STG.E.256).
// One instruction == one full 32B sector.
__device__ __forceinline__ void ldg256(const float* __restrict__ p, float v[8]) {
    asm volatile(
        "ld.global.nc.v8.f32 {%0,%1,%2,%3,%4,%5,%6,%7}, [%8];"
        : "=f"(v[0]), "=f"(v[1]), "=f"(v[2]), "=f"(v[3]),
          "=f"(v[4]), "=f"(v[5]), "=f"(v[6]), "=f"(v[7])
        : "l"(p));
}

__device__ __forceinline__ void stg256(float* __restrict__ p, const float v[8]) {
    asm volatile(
        "st.global.v8.f32 [%0], {%1,%2,%3,%4,%5,%6,%7,%8};"
        :: "l"(p),
           "f"(v[0]), "f"(v[1]), "f"(v[2]), "f"(v[3]),
           "f"(v[4]), "f"(v[5]), "f"(v[6]), "f"(v[7])
        : "memory");
}

// One block = 4 consecutive rows of Sigma (within one batch b: 1024 % 4 == 0).
// 128 threads; thread t owns columns [8t, 8t+8) of all 4 rows — one 32B
// sector per (row, thread). Row masks from one float4 load; column mask
// (8 floats) from one 256-bit load, reused 4x. 4 independent 256-bit Sigma
// loads front-batched (128B in flight per thread), then 4 256-bit stores.
__global__ __launch_bounds__(128) void rvrelu_v8_kernel(
    const float* __restrict__ Sigma,
    const float* __restrict__ mu,
    float*  __restrict__ Sigma_out,
    float4* __restrict__ mu_out4) {

    const int blk  = blockIdx.x;        // 0 .. 32767
    const int row0 = blk << 2;          // first of 4 rows
    const int b    = row0 >> 10;        // batch index
    const int t    = threadIdx.x;       // 0..127

    // 4 row masks in one aligned 16B load (L2-hot)
    const float4 mi4 = __ldg(reinterpret_cast<const float4*>(mu) + blk);

    // fused mu_out: one relu'd float4 store per block
    if (t == 0) {
        float4 r;
        r.x = mi4.x > 0.0f ? mi4.x : 0.0f;
        r.y = mi4.y > 0.0f ? mi4.y : 0.0f;
        r.z = mi4.z > 0.0f ? mi4.z : 0.0f;
        r.w = mi4.w > 0.0f ? mi4.w : 0.0f;
        mu_out4[blk] = r;
    }

    // column mask: mu[b, 8t..8t+7], shared by all 4 rows (L2-hot)
    float mrow[8];
    ldg256(mu + (size_t)b * D + 8 * t, mrow);

    const float mis[ROWS] = {mi4.x, mi4.y, mi4.z, mi4.w};
    const size_t base = (size_t)row0 * D + 8 * t;     // float index

    // Phase 1: issue all 4 independent 256-bit Sigma loads (predicated)
    float v[ROWS][8];
#pragma unroll
    for (int r = 0; r < ROWS; r++) {
        if (mis[r] > 0.0f) {
            ldg256(Sigma + base + (size_t)r * D, v[r]);
        } else {
#pragma unroll
            for (int c = 0; c < 8; c++) v[r][c] = 0.0f;
        }
    }

    // Phase 2: apply column mask and 256-bit store
#pragma unroll
    for (int r = 0; r < ROWS; r++) {
#pragma unroll
        for (int c = 0; c < 8; c++) {
            v[r][c] = (mrow[c] > 0.0f) ? v[r][c] : 0.0f;
        }
        stg256(Sigma_out + base + (size_t)r * D, v[r]);
    }
}

extern "C" void kernel_launch(void* const* d_in, const int* in_sizes, int n_in,
                              void* d_out, int out_size) {
    const float* mu    = (const float*)d_in[0];
    const float* Sigma = (const float*)d_in[1];

    float4* mu_out4   = (float4*)d_out;
    float*  Sigma_out = (float*)d_out + (size_t)B * D;

    // 32768 blocks x 128 threads; 4 Sigma rows per block
    rvrelu_v8_kernel<<<(B * D) / ROWS, 128>>>(Sigma, mu, Sigma_out, mu_out4);
}

// round 7
// speedup vs baseline: 1.0151x; 1.0151x over previous
#include <cuda_runtime.h>
#include <cstddef>

// B=128, D=1024. d_in[0]=mu (131072 f32), d_in[1]=Sigma (128*1024*1024 f32)
// d_out = [mu_out 131072 f32 | Sigma_out 134217728 f32]
//
// Status: 5 configs (MLP4/MLP8, 16B/32B ops, default/streaming policy) all
// measure 6.32-6.41 TB/s DRAM -> mixed-stream bandwidth wall. Traffic is
// algorithmically minimal (compulsory 512 MB stores + ~253 MB active-row
// loads). This round: issue zero-row stores BEFORE the load phase so the
// write stream isn't serialized behind load scoreboards; otherwise keep the
// best-known config (4 rows/block, 256 thr, streaming hints).

static constexpr int B = 128;
static constexpr int D = 1024;
static constexpr int ROWS = 4;

__global__ __launch_bounds__(256) void rvrelu_final_kernel(
    const float4* __restrict__ Sigma,
    const float*  __restrict__ mu,
    float4* __restrict__ Sigma_out,
    float4* __restrict__ mu_out4) {

    const int blk  = blockIdx.x;        // 0 .. 32767
    const int row0 = blk << 2;          // first of 4 rows
    const int b    = row0 >> 10;        // batch index
    const int t    = threadIdx.x;       // 0..255

    // 4 row masks in one aligned 16B load (L2-hot)
    const float4 mi4 = __ldg(reinterpret_cast<const float4*>(mu) + blk);
    const float mis[ROWS] = {mi4.x, mi4.y, mi4.z, mi4.w};

    const size_t base = (size_t)row0 * (D / 4) + t;   // float4 index
    const float4 zero = make_float4(0.0f, 0.0f, 0.0f, 0.0f);

    // Phase 0: drain zero rows into the write stream immediately — no
    // dependence on any outstanding load.
#pragma unroll
    for (int r = 0; r < ROWS; r++) {
        if (mis[r] <= 0.0f) {
            __stcs(Sigma_out + base + (size_t)r * (D / 4), zero);
        }
    }

    // fused mu_out: one relu'd float4 store per block
    if (t == 0) {
        float4 rr;
        rr.x = mi4.x > 0.0f ? mi4.x : 0.0f;
        rr.y = mi4.y > 0.0f ? mi4.y : 0.0f;
        rr.z = mi4.z > 0.0f ? mi4.z : 0.0f;
        rr.w = mi4.w > 0.0f ? mi4.w : 0.0f;
        __stcs(mu_out4 + blk, rr);
    }

    // column mask: mu[b, 4t..4t+3], shared by all 4 rows (L2-hot)
    const float4 mrow =
        __ldg(reinterpret_cast<const float4*>(mu + (size_t)b * D) + t);

    // Phase 1: front-batch all active-row loads (streaming, evict-first)
    float4 v[ROWS];
#pragma unroll
    for (int r = 0; r < ROWS; r++) {
        if (mis[r] > 0.0f) {
            v[r] = __ldcs(Sigma + base + (size_t)r * (D / 4));
        }
    }

    // Phase 2: mask + store active rows
#pragma unroll
    for (int r = 0; r < ROWS; r++) {
        if (mis[r] > 0.0f) {
            float4 o = v[r];
            o.x = mrow.x > 0.0f ? o.x : 0.0f;
            o.y = mrow.y > 0.0f ? o.y : 0.0f;
            o.z = mrow.z > 0.0f ? o.z : 0.0f;
            o.w = mrow.w > 0.0f ? o.w : 0.0f;
            __stcs(Sigma_out + base + (size_t)r * (D / 4), o);
        }
    }
}

extern "C" void kernel_launch(void* const* d_in, const int* in_sizes, int n_in,
                              void* d_out, int out_size) {
    const float* mu    = (const float*)d_in[0];
    const float* Sigma = (const float*)d_in[1];

    float4* mu_out4   = (float4*)d_out;
    float4* Sigma_out = (float4*)((float*)d_out + (size_t)B * D);

    rvrelu_final_kernel<<<(B * D) / ROWS, 256>>>(
        (const float4*)Sigma, mu, Sigma_out, mu_out4);
}